// round 13
// baseline (speedup 1.0000x reference)
#include <cuda_runtime.h>

#define NPT 4096
#define INV_EPS 10.0f
#define ITERS 50
#define FB 296                     // 2 blocks/SM on 148 SMs, all resident
#define NQUADS (NPT / 4)           // 1024 row-quads

// Scratch (static device arrays: allocation-free per harness rules)
__device__ float g_K32[(size_t)NPT * NPT];             // K = exp(-C/eps), fp32 row-major (64 MB, L2-resident)
__device__ __align__(16) float g_colpart[FB * NPT];    // per-block column partials (4.6 MB)
__device__ __align__(16) float g_a[NPT];
__device__ __align__(16) float g_b[NPT];
__device__ float g_part[NPT];
__device__ int   g_ctr;                                // monotone arrive counter (reset by epilogue)

// ---------------------------------------------------------------------------
// Prologue: K_ij = exp(-(|xi0-yj0|+|xi1-yj1|)/eps). Block per row.
// Seeds g_b = 1 (u = v = 0). ~10us (64MB write-bound; exp is ~4us chip-wide).
// ---------------------------------------------------------------------------
__global__ void k_init(const float* __restrict__ x, const float* __restrict__ y) {
    const int i = blockIdx.x;
    const float xi0 = x[2 * i], xi1 = x[2 * i + 1];
    float* __restrict__ Krow = g_K32 + (size_t)i * NPT;
    for (int j = threadIdx.x; j < NPT; j += 256) {
        const float c = fabsf(xi0 - y[2 * j]) + fabsf(xi1 - y[2 * j + 1]);
        Krow[j] = __expf(-INV_EPS * c);
    }
    if (i == 0)
        for (int j = threadIdx.x; j < NPT; j += 256) g_b[j] = 1.0f;
}

// ---------------------------------------------------------------------------
// Fused Sinkhorn iteration, K read ONCE per iteration:
//   a_i = mu/(K b)_i ; colpart[blk] = sum_rows a_i K_ij ; then inline column
//   reduce (blocks 0..63 after grid-wide arrive) : b_j = nu/colsum_j.
// 296 blocks x 256 threads; warp w owns cols [512w,512w+512); quads (4 rows)
// distributed 3-4 per block. K row segments live in registers between the
// dot phase and the scale phase. One __syncthreads per quad (double-buffered
// partials; every thread redundantly folds the 8 warp partials, fixed order).
// Deadlock-free: __launch_bounds__(256,2) + grid 296 <= 2*148 guarantees all
// blocks co-resident before any block can spin.
// ---------------------------------------------------------------------------
__global__ void __launch_bounds__(256, 2) k_iter(float mu, float nu, int target) {
    const int w    = threadIdx.x >> 5;
    const int lane = threadIdx.x & 31;
    const int jq0  = w << 7;                     // float4 base of warp's 512-col slice

    const float4* __restrict__ bp = (const float4*)g_b;
    float4 bseg[4];
#pragma unroll
    for (int q = 0; q < 4; q++) bseg[q] = bp[jq0 + (q << 5) + lane];

    float4 acc[4] = {{0.f,0.f,0.f,0.f},{0.f,0.f,0.f,0.f},
                     {0.f,0.f,0.f,0.f},{0.f,0.f,0.f,0.f}};
    __shared__ float part[2][8][4];

    const int q0 = (int)(((long long)blockIdx.x * NQUADS) / FB);
    const int q1 = (int)(((long long)(blockIdx.x + 1) * NQUADS) / FB);

    for (int qd = q0; qd < q1; qd++) {
        const int rb = qd << 2;
        const int buf = qd & 1;
        float4 kr[4][4];
        float  p[4];
#pragma unroll
        for (int r = 0; r < 4; r++) {
            const float4* __restrict__ Kp =
                (const float4*)(g_K32 + (size_t)(rb + r) * NPT) + jq0;
            float s = 0.f;
#pragma unroll
            for (int q = 0; q < 4; q++) {
                const float4 k = Kp[(q << 5) + lane];
                kr[r][q] = k;
                s += k.x * bseg[q].x + k.y * bseg[q].y
                   + k.z * bseg[q].z + k.w * bseg[q].w;
            }
            p[r] = s;
        }
#pragma unroll
        for (int o = 16; o; o >>= 1) {
            p[0] += __shfl_xor_sync(0xFFFFFFFFu, p[0], o);
            p[1] += __shfl_xor_sync(0xFFFFFFFFu, p[1], o);
            p[2] += __shfl_xor_sync(0xFFFFFFFFu, p[2], o);
            p[3] += __shfl_xor_sync(0xFFFFFFFFu, p[3], o);
        }
        if (lane == 0) {
            part[buf][w][0] = p[0]; part[buf][w][1] = p[1];
            part[buf][w][2] = p[2]; part[buf][w][3] = p[3];
        }
        __syncthreads();                              // single barrier per quad

        float a[4];
#pragma unroll
        for (int r = 0; r < 4; r++) {
            float s = 0.f;
#pragma unroll
            for (int ww = 0; ww < 8; ww++) s += part[buf][ww][r];  // fixed order
            a[r] = mu / s;
        }
        if (threadIdx.x < 4) g_a[rb + threadIdx.x] = a[threadIdx.x];

#pragma unroll
        for (int r = 0; r < 4; r++) {
#pragma unroll
            for (int q = 0; q < 4; q++) {
                acc[q].x = fmaf(a[r], kr[r][q].x, acc[q].x);
                acc[q].y = fmaf(a[r], kr[r][q].y, acc[q].y);
                acc[q].z = fmaf(a[r], kr[r][q].z, acc[q].z);
                acc[q].w = fmaf(a[r], kr[r][q].w, acc[q].w);
            }
        }
    }

    float4* __restrict__ cp = (float4*)(g_colpart + (size_t)blockIdx.x * NPT) + jq0;
#pragma unroll
    for (int q = 0; q < 4; q++) cp[(q << 5) + lane] = acc[q];

    // grid-wide arrive: make colpart visible, then bump the epoch counter
    __threadfence();
    __syncthreads();
    if (threadIdx.x == 0) atomicAdd(&g_ctr, 1);

    // blocks 0..63: wait for all 296 arrivals, then column-reduce -> g_b
    if (blockIdx.x < 64) {
        if (threadIdx.x == 0) {
            volatile int* vc = &g_ctr;
            while (*vc < target) __nanosleep(128);
        }
        __syncthreads();
        __threadfence();

        __shared__ float sp[4][64];
        const int t  = threadIdx.x;
        const int j  = (blockIdx.x << 6) + (t & 63);
        const int cq = t >> 6;                        // 0..3, 74 chunks each
        float s = 0.f;
#pragma unroll 2
        for (int c = cq * 74; c < cq * 74 + 74; c++)
            s += __ldcg(&g_colpart[(size_t)c * NPT + j]);
        sp[cq][t & 63] = s;
        __syncthreads();
        if (t < 64)
            g_b[(blockIdx.x << 6) + t] =
                nu / ((sp[0][t] + sp[1][t]) + (sp[2][t] + sp[3][t]));
    }
}

// ---------------------------------------------------------------------------
// Epilogue: pi_ij = a_i*K_ij*b_j; C recomputed from x,y (y staged in smem);
// per-row deterministic cost partial. Also resets the epoch counter for the
// next graph replay. Block per row, 256 threads.
// ---------------------------------------------------------------------------
__global__ void k_epilogue(const float* __restrict__ x, const float* __restrict__ y,
                           float* __restrict__ pi, float* __restrict__ Cout,
                           int do_write) {
    __shared__ float sy[2 * NPT];                     // 32 KB
    const int i = blockIdx.x;
    const int t = threadIdx.x;
    if (i == 0 && t == 0) g_ctr = 0;                  // reset for next replay

    for (int u = t; u < 2 * NPT; u += 256) sy[u] = y[u];
    __syncthreads();

    const float a   = g_a[i];
    const float xi0 = x[2 * i];
    const float xi1 = x[2 * i + 1];
    const float4* __restrict__ Krow = (const float4*)(g_K32 + (size_t)i * NPT);
    const float4* __restrict__ bp   = (const float4*)g_b;

    float s = 0.f;
    for (int jq = t; jq < NPT / 4; jq += 256) {
        const float4 k4 = __ldcg(Krow + jq);
        const float4 b4 = bp[jq];
        const int j = jq << 2;
        float c[4], p[4];
        c[0] = fabsf(xi0 - sy[2*j + 0]) + fabsf(xi1 - sy[2*j + 1]);
        c[1] = fabsf(xi0 - sy[2*j + 2]) + fabsf(xi1 - sy[2*j + 3]);
        c[2] = fabsf(xi0 - sy[2*j + 4]) + fabsf(xi1 - sy[2*j + 5]);
        c[3] = fabsf(xi0 - sy[2*j + 6]) + fabsf(xi1 - sy[2*j + 7]);
        p[0] = (a * k4.x) * b4.x;  p[1] = (a * k4.y) * b4.y;
        p[2] = (a * k4.z) * b4.z;  p[3] = (a * k4.w) * b4.w;
        s += p[0]*c[0] + p[1]*c[1] + p[2]*c[2] + p[3]*c[3];
        if (do_write) {
            const size_t o = (size_t)i * NPT + j;
            pi[o+0] = p[0]; pi[o+1] = p[1]; pi[o+2] = p[2]; pi[o+3] = p[3];
            Cout[o+0] = c[0]; Cout[o+1] = c[1]; Cout[o+2] = c[2]; Cout[o+3] = c[3];
        }
    }
    __shared__ float sm[256];
    sm[t] = s;
    __syncthreads();
#pragma unroll
    for (int o = 128; o; o >>= 1) {
        if (t < o) sm[t] += sm[t + o];
        __syncthreads();
    }
    if (t == 0) g_part[i] = sm[0];
}

// Deterministic final reduction: cost = sum(pi * C); P=1 so cost^(1/P) = cost.
__global__ void k_final(float* __restrict__ out) {
    __shared__ float sm[1024];
    const int t = threadIdx.x;
    float s = g_part[t] + g_part[t + 1024] + g_part[t + 2048] + g_part[t + 3072];
    sm[t] = s;
    __syncthreads();
#pragma unroll
    for (int o = 512; o; o >>= 1) {
        if (t < o) sm[t] += sm[t + o];
        __syncthreads();
    }
    if (t == 0) out[0] = sm[0];
}

extern "C" void kernel_launch(void* const* d_in, const int* in_sizes, int n_in,
                              void* d_out, int out_size) {
    const float* x = (const float*)d_in[0];
    const float* y = (const float*)d_in[1];
    float* out = (float*)d_out;

    const float mu = 1.0f / (float)NPT + 1e-8f;  // exp(log_mu) == exp(log_nu)
    const float nu = mu;

    k_init<<<NPT, 256>>>(x, y);

    for (int it = 0; it < ITERS; it++)
        k_iter<<<FB, 256>>>(mu, nu, FB * (it + 1));  // fused row+col+bred

    // Output layout (reference return order): [cost, pi (N*N), C (N*N)]
    const size_t nn = (size_t)NPT * NPT;
    const int do_write = (out_size >= (int)(1 + 2 * nn)) ? 1 : 0;
    float* pi = out + 1;
    float* C  = out + 1 + nn;

    k_epilogue<<<NPT, 256>>>(x, y, pi, C, do_write);
    k_final<<<1, 1024>>>(out);
}

// round 15
// speedup vs baseline: 1.9004x; 1.9004x over previous
#include <cuda_runtime.h>

#define NPT 4096
#define INV_EPS 10.0f
#define ITERS 50
#define FB 296                     // 2 blocks/SM on 148 SMs, all resident -> no deadlock
#define NQUADS (NPT / 4)           // 1024 row-quads
#define NRED 128                   // reducer blocks (32 cols each)

// Scratch (static device arrays: allocation-free per harness rules)
__device__ float g_K32[(size_t)NPT * NPT];   // K = exp(-C/eps), fp32 row-major (64 MB, L2-resident)
// colpart layout: [jc (64 col-groups)][blk (296)][c (64)] -> reduce streams contiguously
__device__ __align__(16) float g_colpart[64 * FB * 64];
__device__ __align__(16) float g_a[NPT];
__device__ __align__(16) float g_b[NPT];
__device__ float g_part[NPT];
__device__ int   g_c1;                       // arrive: colpart ready   (target 296*it)
__device__ int   g_c2;                       // arrive: b ready         (target 128*it)

// ---------------------------------------------------------------------------
// Prologue: K_ij = exp(-(|xi0-yj0|+|xi1-yj1|)/eps). Block per row.
// Seeds g_b = 1 (u = v = 0).
// ---------------------------------------------------------------------------
__global__ void k_init(const float* __restrict__ x, const float* __restrict__ y) {
    const int i = blockIdx.x;
    const float xi0 = x[2 * i], xi1 = x[2 * i + 1];
    float* __restrict__ Krow = g_K32 + (size_t)i * NPT;
    for (int j = threadIdx.x; j < NPT; j += 256) {
        const float c = fabsf(xi0 - y[2 * j]) + fabsf(xi1 - y[2 * j + 1]);
        Krow[j] = __expf(-INV_EPS * c);
    }
    if (i == 0)
        for (int j = threadIdx.x; j < NPT; j += 256) g_b[j] = 1.0f;
}

// ---------------------------------------------------------------------------
// Persistent solver: ALL 50 Sinkhorn iterations in one launch.
// Per iteration (K read exactly once):
//   dot phase    : a_i = mu/(K b)_i          (warp-sliced, K rows in registers)
//   scale phase  : colpart[jc][blk][c] += a_i K_ij   (register reuse, no LTS cost)
//   grid sync 1  : monotone counter, all 296 blocks arrive
//   reduce phase : 128 blocks, 32 cols each, contiguous stream, b_j = nu/colsum
//   grid sync 2  : all blocks wait for b, then next iteration
// Deadlock-free: launch_bounds(256,2) + 296 <= 2*148 => all blocks co-resident.
// Counters are monotone within a launch and reset by the epilogue (replay-safe).
// ---------------------------------------------------------------------------
__global__ void __launch_bounds__(256, 2) k_solve(float mu, float nu) {
    const int w    = threadIdx.x >> 5;
    const int lane = threadIdx.x & 31;
    const int jq0  = w << 7;                       // float4 base of warp's 512-col slice

    __shared__ float part[2][8][4];
    __shared__ float sp[8][32];

    const int q0 = (int)(((long long)blockIdx.x * NQUADS) / FB);
    const int q1 = (int)(((long long)(blockIdx.x + 1) * NQUADS) / FB);

    // colpart write targets: j = 512w + 128q + 4*lane
    //   jc = 8w + 2q + (lane>>4), c = 4*(lane&15)
    const int jc_base = (w << 3) + (lane >> 4);
    const int c_col   = (lane & 15) << 2;

    for (int it = 0; it < ITERS; it++) {
        // b segment for this warp's 512 cols (L2; coherent via __ldcg)
        float4 bseg[4];
#pragma unroll
        for (int q = 0; q < 4; q++)
            bseg[q] = __ldcg((const float4*)g_b + jq0 + (q << 5) + lane);

        float4 acc[4] = {{0.f,0.f,0.f,0.f},{0.f,0.f,0.f,0.f},
                         {0.f,0.f,0.f,0.f},{0.f,0.f,0.f,0.f}};

        for (int qd = q0; qd < q1; qd++) {
            const int rb  = qd << 2;
            const int buf = qd & 1;
            float4 kr[4][4];
            float  p[4];
#pragma unroll
            for (int r = 0; r < 4; r++) {
                const float4* __restrict__ Kp =
                    (const float4*)(g_K32 + (size_t)(rb + r) * NPT) + jq0;
                float s = 0.f;
#pragma unroll
                for (int q = 0; q < 4; q++) {
                    const float4 k = Kp[(q << 5) + lane];
                    kr[r][q] = k;
                    s += k.x * bseg[q].x + k.y * bseg[q].y
                       + k.z * bseg[q].z + k.w * bseg[q].w;
                }
                p[r] = s;
            }
#pragma unroll
            for (int o = 16; o; o >>= 1) {
                p[0] += __shfl_xor_sync(0xFFFFFFFFu, p[0], o);
                p[1] += __shfl_xor_sync(0xFFFFFFFFu, p[1], o);
                p[2] += __shfl_xor_sync(0xFFFFFFFFu, p[2], o);
                p[3] += __shfl_xor_sync(0xFFFFFFFFu, p[3], o);
            }
            if (lane == 0) {
                part[buf][w][0] = p[0]; part[buf][w][1] = p[1];
                part[buf][w][2] = p[2]; part[buf][w][3] = p[3];
            }
            __syncthreads();                          // single barrier per quad

            float a[4];
#pragma unroll
            for (int r = 0; r < 4; r++) {
                float s = 0.f;
#pragma unroll
                for (int ww = 0; ww < 8; ww++) s += part[buf][ww][r];  // fixed order
                a[r] = mu / s;
            }
            if (threadIdx.x < 4) g_a[rb + threadIdx.x] = a[threadIdx.x];

#pragma unroll
            for (int r = 0; r < 4; r++) {
#pragma unroll
                for (int q = 0; q < 4; q++) {
                    acc[q].x = fmaf(a[r], kr[r][q].x, acc[q].x);
                    acc[q].y = fmaf(a[r], kr[r][q].y, acc[q].y);
                    acc[q].z = fmaf(a[r], kr[r][q].z, acc[q].z);
                    acc[q].w = fmaf(a[r], kr[r][q].w, acc[q].w);
                }
            }
        }

        // write colpart in reduce-friendly layout (256B contiguous per half-warp)
#pragma unroll
        for (int q = 0; q < 4; q++) {
            const int jc = jc_base + (q << 1);
            float* dst = g_colpart + (((size_t)jc * FB + blockIdx.x) << 6) + c_col;
            *(float4*)dst = acc[q];
        }
        __threadfence();
        __syncthreads();
        if (threadIdx.x == 0) atomicAdd(&g_c1, 1);

        // ---- reduce phase: blocks 0..127, 32 cols each ----
        if (blockIdx.x < NRED) {
            if (threadIdx.x == 0) {
                volatile int* v = &g_c1;
                const int tgt = FB * (it + 1);
                while (*v < tgt) __nanosleep(64);
            }
            __syncthreads();

            const int jc = blockIdx.x >> 1;
            const int h  = (blockIdx.x & 1) << 5;     // 0 or 32
            const int wp = threadIdx.x >> 5;          // 8 block-phases, 37 each
            const float* base = g_colpart + ((size_t)jc * FB << 6) + h + lane;
            float s = 0.f;
#pragma unroll
            for (int bb = 0; bb < 37; bb++)
                s += __ldcg(base + (((size_t)wp * 37 + bb) << 6));
            sp[wp][lane] = s;
            __syncthreads();
            if (threadIdx.x < 32) {
                float t = 0.f;
#pragma unroll
                for (int ph = 0; ph < 8; ph++) t += sp[ph][threadIdx.x];  // fixed order
                g_b[(jc << 6) + h + threadIdx.x] = nu / t;
            }
            __threadfence();
            __syncthreads();
            if (threadIdx.x == 0) atomicAdd(&g_c2, 1);
        }

        // ---- all blocks wait until b is ready ----
        if (threadIdx.x == 0) {
            volatile int* v = &g_c2;
            const int tgt = NRED * (it + 1);
            while (*v < tgt) __nanosleep(64);
        }
        __syncthreads();
    }
}

// ---------------------------------------------------------------------------
// Epilogue: pi_ij = a_i*K_ij*b_j; C recomputed from x,y (y staged in smem);
// per-row deterministic cost partial. Resets epoch counters (replay-safe).
// ---------------------------------------------------------------------------
__global__ void k_epilogue(const float* __restrict__ x, const float* __restrict__ y,
                           float* __restrict__ pi, float* __restrict__ Cout,
                           int do_write) {
    __shared__ float sy[2 * NPT];                     // 32 KB
    const int i = blockIdx.x;
    const int t = threadIdx.x;
    if (i == 0 && t == 0) { g_c1 = 0; g_c2 = 0; }     // reset for next replay

    for (int u = t; u < 2 * NPT; u += 256) sy[u] = y[u];
    __syncthreads();

    const float a   = g_a[i];
    const float xi0 = x[2 * i];
    const float xi1 = x[2 * i + 1];
    const float4* __restrict__ Krow = (const float4*)(g_K32 + (size_t)i * NPT);
    const float4* __restrict__ bp   = (const float4*)g_b;

    float s = 0.f;
    for (int jq = t; jq < NPT / 4; jq += 256) {
        const float4 k4 = __ldcg(Krow + jq);
        const float4 b4 = bp[jq];
        const int j = jq << 2;
        float c[4], p[4];
        c[0] = fabsf(xi0 - sy[2*j + 0]) + fabsf(xi1 - sy[2*j + 1]);
        c[1] = fabsf(xi0 - sy[2*j + 2]) + fabsf(xi1 - sy[2*j + 3]);
        c[2] = fabsf(xi0 - sy[2*j + 4]) + fabsf(xi1 - sy[2*j + 5]);
        c[3] = fabsf(xi0 - sy[2*j + 6]) + fabsf(xi1 - sy[2*j + 7]);
        p[0] = (a * k4.x) * b4.x;  p[1] = (a * k4.y) * b4.y;
        p[2] = (a * k4.z) * b4.z;  p[3] = (a * k4.w) * b4.w;
        s += p[0]*c[0] + p[1]*c[1] + p[2]*c[2] + p[3]*c[3];
        if (do_write) {
            const size_t o = (size_t)i * NPT + j;
            pi[o+0] = p[0]; pi[o+1] = p[1]; pi[o+2] = p[2]; pi[o+3] = p[3];
            Cout[o+0] = c[0]; Cout[o+1] = c[1]; Cout[o+2] = c[2]; Cout[o+3] = c[3];
        }
    }
    __shared__ float sm[256];
    sm[t] = s;
    __syncthreads();
#pragma unroll
    for (int o = 128; o; o >>= 1) {
        if (t < o) sm[t] += sm[t + o];
        __syncthreads();
    }
    if (t == 0) g_part[i] = sm[0];
}

// Deterministic final reduction: cost = sum(pi * C); P=1 so cost^(1/P) = cost.
__global__ void k_final(float* __restrict__ out) {
    __shared__ float sm[1024];
    const int t = threadIdx.x;
    float s = g_part[t] + g_part[t + 1024] + g_part[t + 2048] + g_part[t + 3072];
    sm[t] = s;
    __syncthreads();
#pragma unroll
    for (int o = 512; o; o >>= 1) {
        if (t < o) sm[t] += sm[t + o];
        __syncthreads();
    }
    if (t == 0) out[0] = sm[0];
}

extern "C" void kernel_launch(void* const* d_in, const int* in_sizes, int n_in,
                              void* d_out, int out_size) {
    const float* x = (const float*)d_in[0];
    const float* y = (const float*)d_in[1];
    float* out = (float*)d_out;

    const float mu = 1.0f / (float)NPT + 1e-8f;  // exp(log_mu) == exp(log_nu)
    const float nu = mu;

    k_init<<<NPT, 256>>>(x, y);
    k_solve<<<FB, 256>>>(mu, nu);                // all 50 iterations, one launch

    // Output layout (reference return order): [cost, pi (N*N), C (N*N)]
    const size_t nn = (size_t)NPT * NPT;
    const int do_write = (out_size >= (int)(1 + 2 * nn)) ? 1 : 0;
    float* pi = out + 1;
    float* C  = out + 1 + nn;

    k_epilogue<<<NPT, 256>>>(x, y, pi, C, do_write);
    k_final<<<1, 1024>>>(out);
}